// round 6
// baseline (speedup 1.0000x reference)
#include <cuda_runtime.h>
#include <cfloat>
#include <math.h>
#include <stdint.h>

// Problem constants (fixed shapes from reference)
#define BB 4
#define NN 4096
#define KK 20
#define JH 2048               // kNN j-range half
#define PP (BB * NN * KK)     // 327680 positions
#define NB1 (PP / 256)        // layer1 blocks = 1280
#define NBG (PP / 128)        // gemm blocks   = 2560

// ---------------------------------------------------------------------------
// Scratch in __device__ globals (no allocation allowed in kernel_launch)
// ---------------------------------------------------------------------------
__device__ float g_y1[64  * PP];
__device__ float g_y2[128 * PP];
__device__ float g_y3[128 * PP];
__device__ int   g_idx[BB * NN * KK];
__device__ float g_cs[2 * BB * NN * KK];   // kNN half candidate scores
__device__ int   g_ci[2 * BB * NN * KK];   // kNN half candidate indices
__device__ float g_ps[128 * NBG];
__device__ float g_pq[128 * NBG];
__device__ float g_sc1[64],  g_sh1[64];
__device__ float g_sc2[128], g_sh2[128];
__device__ float g_sc3[128], g_sh3[128];

// ---------------------------------------------------------------------------
// Exact top-20 insert with full (s desc, index asc) ordering.
// ---------------------------------------------------------------------------
#define TOP20_TRY_INSERT(s, j)                                              \
    if ((s) > wv || ((s) == wv && (j) < wj)) {                              \
        bs[wslot] = (s); bi[wslot] = (j);                                   \
        wv = bs[0]; wj = bi[0]; wslot = 0;                                  \
        _Pragma("unroll")                                                   \
        for (int t = 1; t < KK; t++) {                                      \
            bool worse = (bs[t] < wv) || (bs[t] == wv && bi[t] > wj);       \
            if (worse) { wv = bs[t]; wj = bi[t]; wslot = t; }               \
        }                                                                   \
    }

// ---------------------------------------------------------------------------
// K0a: kNN over one j-half (2048 candidates). Maximize s = 2*xi.xj - |xj|^2.
// ---------------------------------------------------------------------------
__global__ void __launch_bounds__(128) knn_half_kernel(
    const float* __restrict__ x, float* __restrict__ cs, int* __restrict__ ci)
{
    extern __shared__ float4 pts[];   // 2048 * 16B = 32KB
    const int b = blockIdx.z;
    const int h = blockIdx.y;
    const int j0 = h * JH;
    const float* xb = x + (size_t)b * NN * 3;
    for (int t = threadIdx.x; t < JH; t += 128) {
        const float* p = xb + (size_t)(j0 + t) * 3;
        float px = p[0], py = p[1], pz = p[2];
        pts[t] = make_float4(px, py, pz, px * px + py * py + pz * pz);
    }
    __syncthreads();

    const int i = blockIdx.x * 128 + threadIdx.x;   // query index
    const float* q = xb + (size_t)i * 3;
    const float qx = 2.f * q[0], qy = 2.f * q[1], qz = 2.f * q[2];

    float bs[KK]; int bi[KK];
#pragma unroll
    for (int t = 0; t < KK; t++) { bs[t] = -FLT_MAX; bi[t] = 0x7fffffff; }
    float wv = -FLT_MAX; int wj = 0x7fffffff; int wslot = 0;

#pragma unroll 4
    for (int t = 0; t < JH; ++t) {
        float4 p = pts[t];
        float s = fmaf(qx, p.x, fmaf(qy, p.y, fmaf(qz, p.z, -p.w)));
        int j = j0 + t;
        TOP20_TRY_INSERT(s, j)
    }

    const size_t base = (((size_t)(b * 2 + h)) * NN + i) * KK;
#pragma unroll
    for (int t = 0; t < KK; t++) { cs[base + t] = bs[t]; ci[base + t] = bi[t]; }
}

// ---------------------------------------------------------------------------
// K0b: merge two half top-20 lists -> exact global top-20 set.
// ---------------------------------------------------------------------------
__global__ void __launch_bounds__(256) knn_merge_kernel(
    const float* __restrict__ cs, const int* __restrict__ ci,
    int* __restrict__ idxo)
{
    const int g = blockIdx.x * 256 + threadIdx.x;   // 0..BB*NN-1
    const int b = g / NN, i = g - b * NN;

    float bs[KK]; int bi[KK];
#pragma unroll
    for (int t = 0; t < KK; t++) { bs[t] = -FLT_MAX; bi[t] = 0x7fffffff; }
    float wv = -FLT_MAX; int wj = 0x7fffffff; int wslot = 0;

#pragma unroll
    for (int h = 0; h < 2; h++) {
        const size_t base = (((size_t)(b * 2 + h)) * NN + i) * KK;
#pragma unroll
        for (int t = 0; t < KK; t++) {
            float s = cs[base + t];
            int   j = ci[base + t];
            TOP20_TRY_INSERT(s, j)
        }
    }

    int* o = idxo + ((size_t)b * NN + i) * KK;
#pragma unroll
    for (int t = 0; t < KK; t++) o[t] = bi[t];
}

// ---------------------------------------------------------------------------
// K1: edge features -> conv1 (64x6) + BN1 partials (proven version).
// ---------------------------------------------------------------------------
__global__ void __launch_bounds__(256) layer1_kernel(
    const float* __restrict__ x,
    const int* __restrict__ idx,
    const float* __restrict__ W1,
    const float* __restrict__ b1,
    float* __restrict__ y1,
    float* __restrict__ ps,
    float* __restrict__ pq)
{
    __shared__ float Wsh[64 * 6];
    __shared__ float bsh[64];
    __shared__ float s_s[64 * 8];
    __shared__ float s_q[64 * 8];
    for (int t = threadIdx.x; t < 64 * 6; t += blockDim.x) Wsh[t] = W1[t];
    if (threadIdx.x < 64) bsh[threadIdx.x] = b1[threadIdx.x];
    __syncthreads();

    const int tid  = threadIdx.x;
    const int lane = tid & 31;
    const int warp = tid >> 5;
    const int p  = blockIdx.x * 256 + tid;
    const int bn = p / KK;
    const int b  = bn / NN;
    const int j  = idx[p];

    const float* xi = x + (size_t)bn * 3;
    const float* xj = x + ((size_t)b * NN + j) * 3;
    float xi0 = xi[0], xi1 = xi[1], xi2 = xi[2];
    float f0 = xj[0] - xi0, f1 = xj[1] - xi1, f2 = xj[2] - xi2;

#pragma unroll 4
    for (int o = 0; o < 64; ++o) {
        const float* w = Wsh + o * 6;
        float a = bsh[o];
        a = fmaf(w[0], f0, a);
        a = fmaf(w[1], f1, a);
        a = fmaf(w[2], f2, a);
        a = fmaf(w[3], xi0, a);
        a = fmaf(w[4], xi1, a);
        a = fmaf(w[5], xi2, a);
        y1[(size_t)o * PP + p] = a;

        float s = a, q = a * a;
#pragma unroll
        for (int m = 16; m > 0; m >>= 1) {
            s += __shfl_xor_sync(0xffffffffu, s, m);
            q += __shfl_xor_sync(0xffffffffu, q, m);
        }
        if (lane == 0) { s_s[o * 8 + warp] = s; s_q[o * 8 + warp] = q; }
    }
    __syncthreads();

    if (tid < 64) {
        float acc = 0.f;
#pragma unroll
        for (int w = 0; w < 8; w++) acc += s_s[tid * 8 + w];
        ps[tid * NB1 + blockIdx.x] = acc;
    } else if (tid < 128) {
        const int o = tid - 64;
        float acc = 0.f;
#pragma unroll
        for (int w = 0; w < 8; w++) acc += s_q[o * 8 + w];
        pq[o * NB1 + blockIdx.x] = acc;
    }
}

// ---------------------------------------------------------------------------
// Reduce per-block partials -> fused BN affine (scale, shift).
// ---------------------------------------------------------------------------
__global__ void reduce_kernel(const float* __restrict__ ps,
                              const float* __restrict__ pq,
                              int nb,
                              const float* __restrict__ gamma,
                              const float* __restrict__ beta,
                              float* __restrict__ scale,
                              float* __restrict__ shift)
{
    const int c = blockIdx.x;
    double s = 0.0, q = 0.0;
    for (int i = threadIdx.x; i < nb; i += 256) {
        s += (double)ps[c * nb + i];
        q += (double)pq[c * nb + i];
    }
    __shared__ double r1[256], r2[256];
    r1[threadIdx.x] = s; r2[threadIdx.x] = q;
    __syncthreads();
    for (int off = 128; off > 0; off >>= 1) {
        if (threadIdx.x < off) {
            r1[threadIdx.x] += r1[threadIdx.x + off];
            r2[threadIdx.x] += r2[threadIdx.x + off];
        }
        __syncthreads();
    }
    if (threadIdx.x == 0) {
        double mean = r1[0] / (double)PP;
        double var  = r2[0] / (double)PP - mean * mean;
        double inv  = (double)gamma[c] / sqrt(var + 1e-5);
        scale[c] = (float)inv;
        shift[c] = (float)((double)beta[c] - mean * inv);
    }
}

// ---------------------------------------------------------------------------
// GEMM (R4-proven): yout[o][p] = bias[o] + sum_c W[o][c]*relu(affine(yin)).
// Scalar FFMA, 128-wide tiles, A staged in 64-deep k-chunks, 2 blocks/SM.
// ---------------------------------------------------------------------------
template <int CIN>
__global__ void __launch_bounds__(256, 2) gemm_kernel(
    const float* __restrict__ yin,
    const float* __restrict__ W,
    const float* __restrict__ bias,
    const float* __restrict__ scale,
    const float* __restrict__ shift,
    float* __restrict__ yout,
    float* __restrict__ ps,
    float* __restrict__ pq)
{
    extern __shared__ float sh[];
    float* Wsh = sh;                  // transposed [CIN][132]
    float* Ash = sh + 132 * CIN;      // [64][128] k-chunk
    const int tid = threadIdx.x;

    for (int t = tid; t < 128 * CIN; t += 256) {
        int o = t / CIN, c = t - o * CIN;
        Wsh[c * 132 + o] = W[t];
    }

    const int pbase = blockIdx.x * 128;
    const int tx = tid & 15;
    const int ty = tid >> 4;

    float acc[8][8];
#pragma unroll
    for (int i = 0; i < 8; i++)
#pragma unroll
        for (int j = 0; j < 8; j++) acc[i][j] = 0.f;

#pragma unroll
    for (int kc = 0; kc < CIN / 64; ++kc) {
        __syncthreads();
        for (int t = tid; t < 64 * 128; t += 256) {
            int c = t >> 7, p = t & 127;
            int cg = kc * 64 + c;
            float v = yin[(size_t)cg * PP + pbase + p];
            v = fmaf(v, scale[cg], shift[cg]);
            Ash[t] = fmaxf(v, 0.f);
        }
        __syncthreads();

#pragma unroll 4
        for (int c = 0; c < 64; ++c) {
            const int cg = kc * 64 + c;
            float4 a0 = *(const float4*)(Ash + c * 128 + tx * 4);
            float4 a1 = *(const float4*)(Ash + c * 128 + 64 + tx * 4);
            float4 w0 = *(const float4*)(Wsh + cg * 132 + ty * 4);
            float4 w1 = *(const float4*)(Wsh + cg * 132 + 64 + ty * 4);
            float a[8] = {a0.x, a0.y, a0.z, a0.w, a1.x, a1.y, a1.z, a1.w};
            float w[8] = {w0.x, w0.y, w0.z, w0.w, w1.x, w1.y, w1.z, w1.w};
#pragma unroll
            for (int i = 0; i < 8; i++)
#pragma unroll
                for (int j = 0; j < 8; j++)
                    acc[i][j] = fmaf(w[i], a[j], acc[i][j]);
        }
    }

#pragma unroll
    for (int i = 0; i < 8; i++) {
        const int o = (i < 4) ? (ty * 4 + i) : (64 + ty * 4 + (i - 4));
        const float bo = bias[o];
        float v0 = acc[i][0] + bo, v1 = acc[i][1] + bo;
        float v2 = acc[i][2] + bo, v3 = acc[i][3] + bo;
        float v4 = acc[i][4] + bo, v5 = acc[i][5] + bo;
        float v6 = acc[i][6] + bo, v7 = acc[i][7] + bo;
        float* dst = yout + (size_t)o * PP + pbase;
        *(float4*)(dst + tx * 4)      = make_float4(v0, v1, v2, v3);
        *(float4*)(dst + 64 + tx * 4) = make_float4(v4, v5, v6, v7);

        float s = v0 + v1 + v2 + v3 + v4 + v5 + v6 + v7;
        float q = v0 * v0 + v1 * v1 + v2 * v2 + v3 * v3
                + v4 * v4 + v5 * v5 + v6 * v6 + v7 * v7;
#pragma unroll
        for (int m = 8; m > 0; m >>= 1) {
            s += __shfl_xor_sync(0xffffffffu, s, m, 16);
            q += __shfl_xor_sync(0xffffffffu, q, m, 16);
        }
        if (tx == 0) {
            ps[(size_t)o * NBG + blockIdx.x] = s;
            pq[(size_t)o * NBG + blockIdx.x] = q;
        }
    }
}

// ---------------------------------------------------------------------------
// Max over k with final BN affine applied elementwise (proven version).
// ---------------------------------------------------------------------------
__global__ void maxk_kernel(const float* __restrict__ y3,
                            const float* __restrict__ scale,
                            const float* __restrict__ shift,
                            float* __restrict__ out)
{
    const int n = blockIdx.x * blockDim.x + threadIdx.x;
    const int o = blockIdx.y;
    const int b = blockIdx.z;
    const float sc = scale[o], sf = shift[o];
    const float4* base =
        (const float4*)(y3 + (size_t)o * PP + ((size_t)b * NN + n) * KK);
    float m = -FLT_MAX;
#pragma unroll
    for (int q = 0; q < 5; ++q) {
        float4 v = base[q];
        m = fmaxf(m, fmaf(v.x, sc, sf));
        m = fmaxf(m, fmaf(v.y, sc, sf));
        m = fmaxf(m, fmaf(v.z, sc, sf));
        m = fmaxf(m, fmaf(v.w, sc, sf));
    }
    out[((size_t)b * 128 + o) * NN + n] = m;
}

// ---------------------------------------------------------------------------
// Launcher: graph-capturable, allocation-free.
// ---------------------------------------------------------------------------
extern "C" void kernel_launch(void* const* d_in, const int* in_sizes, int n_in,
                              void* d_out, int out_size)
{
    const float* x   = (const float*)d_in[0];
    const float* W1  = (const float*)d_in[1];
    const float* b1  = (const float*)d_in[2];
    const float* g1  = (const float*)d_in[3];
    const float* be1 = (const float*)d_in[4];
    const float* W2  = (const float*)d_in[5];
    const float* b2  = (const float*)d_in[6];
    const float* g2  = (const float*)d_in[7];
    const float* be2 = (const float*)d_in[8];
    const float* W3  = (const float*)d_in[9];
    const float* b3  = (const float*)d_in[10];
    const float* g3  = (const float*)d_in[11];
    const float* be3 = (const float*)d_in[12];
    float* out = (float*)d_out;

    void *y1p, *y2p, *y3p, *idxp, *csp, *cip, *psp, *pqp;
    void *sc1p, *sh1p, *sc2p, *sh2p, *sc3p, *sh3p;
    cudaGetSymbolAddress(&y1p,  g_y1);
    cudaGetSymbolAddress(&y2p,  g_y2);
    cudaGetSymbolAddress(&y3p,  g_y3);
    cudaGetSymbolAddress(&idxp, g_idx);
    cudaGetSymbolAddress(&csp,  g_cs);
    cudaGetSymbolAddress(&cip,  g_ci);
    cudaGetSymbolAddress(&psp,  g_ps);
    cudaGetSymbolAddress(&pqp,  g_pq);
    cudaGetSymbolAddress(&sc1p, g_sc1);  cudaGetSymbolAddress(&sh1p, g_sh1);
    cudaGetSymbolAddress(&sc2p, g_sc2);  cudaGetSymbolAddress(&sh2p, g_sh2);
    cudaGetSymbolAddress(&sc3p, g_sc3);  cudaGetSymbolAddress(&sh3p, g_sh3);

    const int smemK   = JH * 16;                           // 32768 B
    const int smem64  = (132 * 64  + 64 * 128) * 4;        // 66560 B
    const int smem128 = (132 * 128 + 64 * 128) * 4;        // 100352 B
    cudaFuncSetAttribute(knn_half_kernel,  cudaFuncAttributeMaxDynamicSharedMemorySize, smemK);
    cudaFuncSetAttribute(gemm_kernel<64>,  cudaFuncAttributeMaxDynamicSharedMemorySize, smem64);
    cudaFuncSetAttribute(gemm_kernel<128>, cudaFuncAttributeMaxDynamicSharedMemorySize, smem128);

    // K0: kNN (split-j halves, then exact merge)
    knn_half_kernel<<<dim3(NN / 128, 2, BB), 128, smemK>>>(x, (float*)csp, (int*)cip);
    knn_merge_kernel<<<(BB * NN) / 256, 256>>>((const float*)csp, (const int*)cip,
                                               (int*)idxp);

    // K1: edge features + conv1 (raw) + BN1 partials
    layer1_kernel<<<NB1, 256>>>(x, (const int*)idxp, W1, b1, (float*)y1p,
                                (float*)psp, (float*)pqp);
    reduce_kernel<<<64, 256>>>((const float*)psp, (const float*)pqp, NB1,
                               g1, be1, (float*)sc1p, (float*)sh1p);

    // conv2 on relu(BN1(y1)) + BN2 partials
    gemm_kernel<64><<<NBG, 256, smem64>>>((const float*)y1p, W2, b2,
                                          (const float*)sc1p, (const float*)sh1p,
                                          (float*)y2p, (float*)psp, (float*)pqp);
    reduce_kernel<<<128, 256>>>((const float*)psp, (const float*)pqp, NBG,
                                g2, be2, (float*)sc2p, (float*)sh2p);

    // conv3 on relu(BN2(y2)) + BN3 partials
    gemm_kernel<128><<<NBG, 256, smem128>>>((const float*)y2p, W3, b3,
                                            (const float*)sc2p, (const float*)sh2p,
                                            (float*)y3p, (float*)psp, (float*)pqp);
    reduce_kernel<<<128, 256>>>((const float*)psp, (const float*)pqp, NBG,
                                g3, be3, (float*)sc3p, (float*)sh3p);

    // BN3 affine + max over k
    maxk_kernel<<<dim3(NN / 256, 128, BB), 256>>>((const float*)y3p,
                                                  (const float*)sc3p, (const float*)sh3p,
                                                  out);
}

// round 7
// speedup vs baseline: 1.2581x; 1.2581x over previous
#include <cuda_runtime.h>
#include <cfloat>
#include <math.h>
#include <stdint.h>

// Problem constants (fixed shapes from reference)
#define BB 4
#define NN 4096
#define KK 20
#define PP (BB * NN * KK)     // 327680 positions
#define NB1 (PP / 256)        // layer1 blocks = 1280
#define NBG (PP / 128)        // gemm blocks   = 2560

// ---------------------------------------------------------------------------
// Scratch in __device__ globals (no allocation allowed in kernel_launch)
// ---------------------------------------------------------------------------
__device__ float g_y1[64  * PP];
__device__ float g_y2[128 * PP];
__device__ float g_y3[128 * PP];
__device__ int   g_idx[BB * NN * KK];
__device__ float g_ps[128 * NBG];
__device__ float g_pq[128 * NBG];
__device__ float g_sc1[64],  g_sh1[64];
__device__ float g_sc2[128], g_sh2[128];
__device__ float g_sc3[128], g_sh3[128];

// ---------------------------------------------------------------------------
// Packed fp32x2 helpers (FFMA2 — ptxas never emits this from C++).
// Correctness of this path was validated in an earlier passing round.
// ---------------------------------------------------------------------------
__device__ __forceinline__ unsigned long long splat2(float v) {
    unsigned long long r;
    asm("mov.b64 %0, {%1, %1};" : "=l"(r) : "f"(v));
    return r;
}
__device__ __forceinline__ void ffma2(unsigned long long& d,
                                      unsigned long long a,
                                      unsigned long long b) {
    asm("fma.rn.f32x2 %0, %1, %2, %0;" : "+l"(d) : "l"(a), "l"(b));
}
__device__ __forceinline__ float2 unpack2(unsigned long long v) {
    float2 f;
    asm("mov.b64 {%0, %1}, %2;" : "=f"(f.x), "=f"(f.y) : "l"(v));
    return f;
}

// ---------------------------------------------------------------------------
// K0: brute-force exact kNN (k=20) per batch.
// Register-resident top-20: constant-index predicated updates ONLY
// (dynamic-index stores would demote the arrays to local memory).
// ---------------------------------------------------------------------------
__global__ void knn_kernel(const float* __restrict__ x, int* __restrict__ idxo)
{
    extern __shared__ float4 pts[];   // 4096 * 16B = 64KB
    const int b = blockIdx.y;
    const float* xb = x + (size_t)b * NN * 3;
    for (int t = threadIdx.x; t < NN; t += blockDim.x) {
        float px = xb[t * 3 + 0], py = xb[t * 3 + 1], pz = xb[t * 3 + 2];
        pts[t] = make_float4(px, py, pz, px * px + py * py + pz * pz);
    }
    __syncthreads();

    const int i = blockIdx.x * blockDim.x + threadIdx.x;
    float4 q = pts[i];
    const float qx = 2.f * q.x, qy = 2.f * q.y, qz = 2.f * q.z;

    float bs[KK]; int bi[KK];
#pragma unroll
    for (int t = 0; t < KK; t++) { bs[t] = -FLT_MAX; bi[t] = 0x7fffffff; }
    float wmin = -FLT_MAX;

#pragma unroll 4
    for (int j = 0; j < NN; ++j) {
        float4 p = pts[j];
        float s = fmaf(qx, p.x, fmaf(qy, p.y, fmaf(qz, p.z, -p.w)));
        if (s > wmin) {
            int   ws = 0;
            float wv = bs[0];
            int   wi = bi[0];
#pragma unroll
            for (int t = 1; t < KK; t++) {
                bool worse = (bs[t] < wv) || (bs[t] == wv && bi[t] > wi);
                if (worse) { ws = t; wv = bs[t]; wi = bi[t]; }
            }
            float nm = FLT_MAX;
#pragma unroll
            for (int t = 0; t < KK; t++) {
                if (t == ws) { bs[t] = s; bi[t] = j; }
                nm = fminf(nm, bs[t]);
            }
            wmin = nm;
        }
    }

    int* o = idxo + ((size_t)b * NN + i) * KK;
#pragma unroll
    for (int t = 0; t < KK; t++) o[t] = bi[t];
}

// ---------------------------------------------------------------------------
// K1: edge features -> conv1 (64x6) + BN1 partials (proven version).
// ---------------------------------------------------------------------------
__global__ void __launch_bounds__(256) layer1_kernel(
    const float* __restrict__ x,
    const int* __restrict__ idx,
    const float* __restrict__ W1,
    const float* __restrict__ b1,
    float* __restrict__ y1,
    float* __restrict__ ps,
    float* __restrict__ pq)
{
    __shared__ float Wsh[64 * 6];
    __shared__ float bsh[64];
    __shared__ float s_s[64 * 8];
    __shared__ float s_q[64 * 8];
    for (int t = threadIdx.x; t < 64 * 6; t += blockDim.x) Wsh[t] = W1[t];
    if (threadIdx.x < 64) bsh[threadIdx.x] = b1[threadIdx.x];
    __syncthreads();

    const int tid  = threadIdx.x;
    const int lane = tid & 31;
    const int warp = tid >> 5;
    const int p  = blockIdx.x * 256 + tid;
    const int bn = p / KK;
    const int b  = bn / NN;
    const int j  = idx[p];

    const float* xi = x + (size_t)bn * 3;
    const float* xj = x + ((size_t)b * NN + j) * 3;
    float xi0 = xi[0], xi1 = xi[1], xi2 = xi[2];
    float f0 = xj[0] - xi0, f1 = xj[1] - xi1, f2 = xj[2] - xi2;

#pragma unroll 4
    for (int o = 0; o < 64; ++o) {
        const float* w = Wsh + o * 6;
        float a = bsh[o];
        a = fmaf(w[0], f0, a);
        a = fmaf(w[1], f1, a);
        a = fmaf(w[2], f2, a);
        a = fmaf(w[3], xi0, a);
        a = fmaf(w[4], xi1, a);
        a = fmaf(w[5], xi2, a);
        y1[(size_t)o * PP + p] = a;

        float s = a, q = a * a;
#pragma unroll
        for (int m = 16; m > 0; m >>= 1) {
            s += __shfl_xor_sync(0xffffffffu, s, m);
            q += __shfl_xor_sync(0xffffffffu, q, m);
        }
        if (lane == 0) { s_s[o * 8 + warp] = s; s_q[o * 8 + warp] = q; }
    }
    __syncthreads();

    if (tid < 64) {
        float acc = 0.f;
#pragma unroll
        for (int w = 0; w < 8; w++) acc += s_s[tid * 8 + w];
        ps[tid * NB1 + blockIdx.x] = acc;
    } else if (tid < 128) {
        const int o = tid - 64;
        float acc = 0.f;
#pragma unroll
        for (int w = 0; w < 8; w++) acc += s_q[o * 8 + w];
        pq[o * NB1 + blockIdx.x] = acc;
    }
}

// ---------------------------------------------------------------------------
// Reduce per-block partials -> fused BN affine (scale, shift).
// ---------------------------------------------------------------------------
__global__ void reduce_kernel(const float* __restrict__ ps,
                              const float* __restrict__ pq,
                              int nb,
                              const float* __restrict__ gamma,
                              const float* __restrict__ beta,
                              float* __restrict__ scale,
                              float* __restrict__ shift)
{
    const int c = blockIdx.x;
    double s = 0.0, q = 0.0;
    for (int i = threadIdx.x; i < nb; i += 256) {
        s += (double)ps[c * nb + i];
        q += (double)pq[c * nb + i];
    }
    __shared__ double r1[256], r2[256];
    r1[threadIdx.x] = s; r2[threadIdx.x] = q;
    __syncthreads();
    for (int off = 128; off > 0; off >>= 1) {
        if (threadIdx.x < off) {
            r1[threadIdx.x] += r1[threadIdx.x + off];
            r2[threadIdx.x] += r2[threadIdx.x + off];
        }
        __syncthreads();
    }
    if (threadIdx.x == 0) {
        double mean = r1[0] / (double)PP;
        double var  = r2[0] / (double)PP - mean * mean;
        double inv  = (double)gamma[c] / sqrt(var + 1e-5);
        scale[c] = (float)inv;
        shift[c] = (float)((double)beta[c] - mean * inv);
    }
}

// ---------------------------------------------------------------------------
// GEMM: yout[o][p] = bias[o] + sum_c W[o][c] * relu(scale[c]*yin[c][p]+shift[c])
// FFMA2 (fma.rn.f32x2) inner loop: 32 packed FMAs + 8 splats per k-step
// vs 64 scalar FFMA. A staged in 64-deep k-chunks (2 blocks/SM at CIN=128).
// W staged transposed [CIN][132]. Epilogue: BN partial sums per block.
// ---------------------------------------------------------------------------
template <int CIN>
__global__ void __launch_bounds__(256, 2) gemm_kernel(
    const float* __restrict__ yin,
    const float* __restrict__ W,
    const float* __restrict__ bias,
    const float* __restrict__ scale,
    const float* __restrict__ shift,
    float* __restrict__ yout,
    float* __restrict__ ps,
    float* __restrict__ pq)
{
    extern __shared__ float sh[];
    float* Wsh = sh;                  // transposed [CIN][132]
    float* Ash = sh + 132 * CIN;      // [64][128] k-chunk
    const int tid = threadIdx.x;

    for (int t = tid; t < 128 * CIN; t += 256) {
        int o = t / CIN, c = t - o * CIN;
        Wsh[c * 132 + o] = W[t];
    }

    const int pbase = blockIdx.x * 128;
    const int tx = tid & 15;   // position fragment: cols tx*4 and 64+tx*4
    const int ty = tid >> 4;   // output   fragment: rows ty*4 and 64+ty*4

    unsigned long long acc[8][4];
#pragma unroll
    for (int i = 0; i < 8; i++)
#pragma unroll
        for (int jp = 0; jp < 4; jp++) acc[i][jp] = 0ULL;

#pragma unroll
    for (int kc = 0; kc < CIN / 64; ++kc) {
        __syncthreads();   // Wsh ready (kc=0) / protect Ash before restage
        for (int t = tid; t < 64 * 128; t += 256) {
            int c = t >> 7, p = t & 127;
            int cg = kc * 64 + c;
            float v = yin[(size_t)cg * PP + pbase + p];
            v = fmaf(v, scale[cg], shift[cg]);
            Ash[t] = fmaxf(v, 0.f);
        }
        __syncthreads();

#pragma unroll 4
        for (int c = 0; c < 64; ++c) {
            const int cg = kc * 64 + c;
            ulonglong2 A0 = *(const ulonglong2*)(Ash + c * 128 + tx * 4);
            ulonglong2 A1 = *(const ulonglong2*)(Ash + c * 128 + 64 + tx * 4);
            unsigned long long av[4] = {A0.x, A0.y, A1.x, A1.y};
            float4 w0 = *(const float4*)(Wsh + cg * 132 + ty * 4);
            float4 w1 = *(const float4*)(Wsh + cg * 132 + 64 + ty * 4);
            float wf[8] = {w0.x, w0.y, w0.z, w0.w, w1.x, w1.y, w1.z, w1.w};
#pragma unroll
            for (int i = 0; i < 8; i++) {
                unsigned long long wsp = splat2(wf[i]);
#pragma unroll
                for (int jp = 0; jp < 4; jp++) ffma2(acc[i][jp], wsp, av[jp]);
            }
        }
    }

#pragma unroll
    for (int i = 0; i < 8; i++) {
        const int o = (i < 4) ? (ty * 4 + i) : (64 + ty * 4 + (i - 4));
        const float bo = bias[o];
        float2 p0 = unpack2(acc[i][0]);
        float2 p1 = unpack2(acc[i][1]);
        float2 p2 = unpack2(acc[i][2]);
        float2 p3 = unpack2(acc[i][3]);
        float v0 = p0.x + bo, v1 = p0.y + bo, v2 = p1.x + bo, v3 = p1.y + bo;
        float v4 = p2.x + bo, v5 = p2.y + bo, v6 = p3.x + bo, v7 = p3.y + bo;
        float* dst = yout + (size_t)o * PP + pbase;
        *(float4*)(dst + tx * 4)      = make_float4(v0, v1, v2, v3);
        *(float4*)(dst + 64 + tx * 4) = make_float4(v4, v5, v6, v7);

        float s = v0 + v1 + v2 + v3 + v4 + v5 + v6 + v7;
        float q = v0 * v0 + v1 * v1 + v2 * v2 + v3 * v3
                + v4 * v4 + v5 * v5 + v6 * v6 + v7 * v7;
#pragma unroll
        for (int m = 8; m > 0; m >>= 1) {
            s += __shfl_xor_sync(0xffffffffu, s, m, 16);
            q += __shfl_xor_sync(0xffffffffu, q, m, 16);
        }
        if (tx == 0) {
            ps[(size_t)o * NBG + blockIdx.x] = s;
            pq[(size_t)o * NBG + blockIdx.x] = q;
        }
    }
}

// ---------------------------------------------------------------------------
// Max over k with final BN affine applied elementwise (proven version).
// ---------------------------------------------------------------------------
__global__ void maxk_kernel(const float* __restrict__ y3,
                            const float* __restrict__ scale,
                            const float* __restrict__ shift,
                            float* __restrict__ out)
{
    const int n = blockIdx.x * blockDim.x + threadIdx.x;
    const int o = blockIdx.y;
    const int b = blockIdx.z;
    const float sc = scale[o], sf = shift[o];
    const float4* base =
        (const float4*)(y3 + (size_t)o * PP + ((size_t)b * NN + n) * KK);
    float m = -FLT_MAX;
#pragma unroll
    for (int q = 0; q < 5; ++q) {
        float4 v = base[q];
        m = fmaxf(m, fmaf(v.x, sc, sf));
        m = fmaxf(m, fmaf(v.y, sc, sf));
        m = fmaxf(m, fmaf(v.z, sc, sf));
        m = fmaxf(m, fmaf(v.w, sc, sf));
    }
    out[((size_t)b * 128 + o) * NN + n] = m;
}

// ---------------------------------------------------------------------------
// Launcher: graph-capturable, allocation-free.
// ---------------------------------------------------------------------------
extern "C" void kernel_launch(void* const* d_in, const int* in_sizes, int n_in,
                              void* d_out, int out_size)
{
    const float* x   = (const float*)d_in[0];
    const float* W1  = (const float*)d_in[1];
    const float* b1  = (const float*)d_in[2];
    const float* g1  = (const float*)d_in[3];
    const float* be1 = (const float*)d_in[4];
    const float* W2  = (const float*)d_in[5];
    const float* b2  = (const float*)d_in[6];
    const float* g2  = (const float*)d_in[7];
    const float* be2 = (const float*)d_in[8];
    const float* W3  = (const float*)d_in[9];
    const float* b3  = (const float*)d_in[10];
    const float* g3  = (const float*)d_in[11];
    const float* be3 = (const float*)d_in[12];
    float* out = (float*)d_out;

    void *y1p, *y2p, *y3p, *idxp, *psp, *pqp;
    void *sc1p, *sh1p, *sc2p, *sh2p, *sc3p, *sh3p;
    cudaGetSymbolAddress(&y1p,  g_y1);
    cudaGetSymbolAddress(&y2p,  g_y2);
    cudaGetSymbolAddress(&y3p,  g_y3);
    cudaGetSymbolAddress(&idxp, g_idx);
    cudaGetSymbolAddress(&psp,  g_ps);
    cudaGetSymbolAddress(&pqp,  g_pq);
    cudaGetSymbolAddress(&sc1p, g_sc1);  cudaGetSymbolAddress(&sh1p, g_sh1);
    cudaGetSymbolAddress(&sc2p, g_sc2);  cudaGetSymbolAddress(&sh2p, g_sh2);
    cudaGetSymbolAddress(&sc3p, g_sc3);  cudaGetSymbolAddress(&sh3p, g_sh3);

    const int smem64  = (132 * 64  + 64 * 128) * 4;        // 66560 B
    const int smem128 = (132 * 128 + 64 * 128) * 4;        // 100352 B
    cudaFuncSetAttribute(knn_kernel,       cudaFuncAttributeMaxDynamicSharedMemorySize, 65536);
    cudaFuncSetAttribute(gemm_kernel<64>,  cudaFuncAttributeMaxDynamicSharedMemorySize, smem64);
    cudaFuncSetAttribute(gemm_kernel<128>, cudaFuncAttributeMaxDynamicSharedMemorySize, smem128);

    // K0: kNN
    knn_kernel<<<dim3(NN / 128, BB), 128, 65536>>>(x, (int*)idxp);

    // K1: edge features + conv1 (raw) + BN1 partials
    layer1_kernel<<<NB1, 256>>>(x, (const int*)idxp, W1, b1, (float*)y1p,
                                (float*)psp, (float*)pqp);
    reduce_kernel<<<64, 256>>>((const float*)psp, (const float*)pqp, NB1,
                               g1, be1, (float*)sc1p, (float*)sh1p);

    // conv2 on relu(BN1(y1)) + BN2 partials
    gemm_kernel<64><<<NBG, 256, smem64>>>((const float*)y1p, W2, b2,
                                          (const float*)sc1p, (const float*)sh1p,
                                          (float*)y2p, (float*)psp, (float*)pqp);
    reduce_kernel<<<128, 256>>>((const float*)psp, (const float*)pqp, NBG,
                                g2, be2, (float*)sc2p, (float*)sh2p);

    // conv3 on relu(BN2(y2)) + BN3 partials
    gemm_kernel<128><<<NBG, 256, smem128>>>((const float*)y2p, W3, b3,
                                            (const float*)sc2p, (const float*)sh2p,
                                            (float*)y3p, (float*)psp, (float*)pqp);
    reduce_kernel<<<128, 256>>>((const float*)psp, (const float*)pqp, NBG,
                                g3, be3, (float*)sc3p, (float*)sh3p);

    // BN3 affine + max over k
    maxk_kernel<<<dim3(NN / 256, 128, BB), 256>>>((const float*)y3p,
                                                  (const float*)sc3p, (const float*)sh3p,
                                                  out);
}

// round 8
// speedup vs baseline: 1.8744x; 1.4898x over previous
#include <cuda_runtime.h>
#include <cfloat>
#include <math.h>
#include <stdint.h>

// Problem constants (fixed shapes from reference)
#define BB 4
#define NN 4096
#define KK 20
#define QPB 8                 // queries per block (1 per warp)
#define PP (BB * NN * KK)     // 327680 positions
#define NB1 (PP / 256)        // layer1 blocks = 1280
#define NBG (PP / 128)        // gemm blocks   = 2560

// ---------------------------------------------------------------------------
// Scratch in __device__ globals (no allocation allowed in kernel_launch)
// ---------------------------------------------------------------------------
__device__ float g_y1[64  * PP];
__device__ float g_y2[128 * PP];
__device__ float g_y3[128 * PP];
__device__ int   g_idx[BB * NN * KK];
__device__ float g_ps[128 * NBG];
__device__ float g_pq[128 * NBG];
__device__ float g_sc1[64],  g_sh1[64];
__device__ float g_sc2[128], g_sh2[128];
__device__ float g_sc3[128], g_sh3[128];

// ---------------------------------------------------------------------------
// Packed fp32x2 helpers (FFMA2)
// ---------------------------------------------------------------------------
__device__ __forceinline__ unsigned long long splat2(float v) {
    unsigned long long r;
    asm("mov.b64 %0, {%1, %1};" : "=l"(r) : "f"(v));
    return r;
}
__device__ __forceinline__ void ffma2(unsigned long long& d,
                                      unsigned long long a,
                                      unsigned long long b) {
    asm("fma.rn.f32x2 %0, %1, %2, %0;" : "+l"(d) : "l"(a), "l"(b));
}
__device__ __forceinline__ float2 unpack2(unsigned long long v) {
    float2 f;
    asm("mov.b64 {%0, %1}, %2;" : "=f"(f.x), "=f"(f.y) : "l"(v));
    return f;
}

// Orderable uint key: ascending float order -> ascending unsigned order.
__device__ __forceinline__ unsigned okey(float f) {
    unsigned u = __float_as_uint(f);
    return (u & 0x80000000u) ? ~u : (u | 0x80000000u);
}

// ---------------------------------------------------------------------------
// Dummy kernel: shifts the ncu capture window (launch #4) onto knn.
// ---------------------------------------------------------------------------
__global__ void dummy_kernel() {}

// ---------------------------------------------------------------------------
// K0: warp-cooperative exact kNN (k=20). One query per warp; top-20 list
// distributed one slot per lane (lanes 0..19). Ballot-driven inserts with
// uniform control flow. Exact top_k semantics:
//  - candidates processed in ascending j (chunk base + __ffs order)
//  - strict s > wmin: ties lose to existing (lower-index) holders
//  - eviction: minimal (s, then larger j first) -> kept ties are lowest-index
// s = 2*xi.xj - |xj|^2 (monotone in reference pd).
// ---------------------------------------------------------------------------
__global__ void __launch_bounds__(256) knn_warp_kernel(
    const float* __restrict__ x, int* __restrict__ idxo)
{
    extern __shared__ float4 pts[];   // 4096 * 16B = 64KB
    const int b = blockIdx.y;
    const float* xb = x + (size_t)b * NN * 3;
    const int tid = threadIdx.x, lane = tid & 31, w = tid >> 5;

    for (int t = tid; t < NN; t += 256) {
        float px = xb[t * 3 + 0], py = xb[t * 3 + 1], pz = xb[t * 3 + 2];
        pts[t] = make_float4(px, py, pz, px * px + py * py + pz * pz);
    }
    __syncthreads();

    const int i = blockIdx.x * QPB + w;   // this warp's query
    float4 q = pts[i];
    const float qx = 2.f * q.x, qy = 2.f * q.y, qz = 2.f * q.z;

    // Distributed list: lanes 0..19 are slots; lanes 20..31 sentinels (+inf,
    // never evicted, never the min).
    float my_s = (lane < KK) ? -FLT_MAX : FLT_MAX;
    int   my_j = 0x7fffffff;
    float wmin = -FLT_MAX;   // min over the 20 slots (uniform across warp)

    for (int jc = 0; jc < NN; jc += 32) {
        float4 p = pts[jc + lane];
        float s = fmaf(qx, p.x, fmaf(qy, p.y, fmaf(qz, p.z, -p.w)));
        unsigned mask = __ballot_sync(0xffffffffu, s > wmin);
        while (mask) {
            const int l = __ffs(mask) - 1;   // ascending lane = ascending j
            mask &= mask - 1;
            const float sc = __shfl_sync(0xffffffffu, s, l);
            if (sc > wmin) {                 // uniform re-check (wmin may rise)
                const int jj = jc + l;
                // eviction argmin over slots: key = (s asc | ~j)
                unsigned long long key =
                    ((unsigned long long)okey(my_s) << 32) | (unsigned)(~my_j);
                unsigned long long kmin = key;
#pragma unroll
                for (int d = 16; d; d >>= 1) {
                    unsigned long long o = __shfl_xor_sync(0xffffffffu, kmin, d);
                    kmin = (o < kmin) ? o : kmin;
                }
                unsigned em = __ballot_sync(0xffffffffu, key == kmin);
                if (lane == __ffs(em) - 1) { my_s = sc; my_j = jj; }
                // recompute wmin (sentinel lanes hold FLT_MAX)
                float m = my_s;
#pragma unroll
                for (int d = 16; d; d >>= 1)
                    m = fminf(m, __shfl_xor_sync(0xffffffffu, m, d));
                wmin = m;
            }
        }
    }

    if (lane < KK)
        idxo[((size_t)b * NN + i) * KK + lane] = my_j;
}

// ---------------------------------------------------------------------------
// K1: edge features -> conv1 (64x6) + BN1 partials (proven version).
// ---------------------------------------------------------------------------
__global__ void __launch_bounds__(256) layer1_kernel(
    const float* __restrict__ x,
    const int* __restrict__ idx,
    const float* __restrict__ W1,
    const float* __restrict__ b1,
    float* __restrict__ y1,
    float* __restrict__ ps,
    float* __restrict__ pq)
{
    __shared__ float Wsh[64 * 6];
    __shared__ float bsh[64];
    __shared__ float s_s[64 * 8];
    __shared__ float s_q[64 * 8];
    for (int t = threadIdx.x; t < 64 * 6; t += blockDim.x) Wsh[t] = W1[t];
    if (threadIdx.x < 64) bsh[threadIdx.x] = b1[threadIdx.x];
    __syncthreads();

    const int tid  = threadIdx.x;
    const int lane = tid & 31;
    const int warp = tid >> 5;
    const int p  = blockIdx.x * 256 + tid;
    const int bn = p / KK;
    const int b  = bn / NN;
    const int j  = idx[p];

    const float* xi = x + (size_t)bn * 3;
    const float* xj = x + ((size_t)b * NN + j) * 3;
    float xi0 = xi[0], xi1 = xi[1], xi2 = xi[2];
    float f0 = xj[0] - xi0, f1 = xj[1] - xi1, f2 = xj[2] - xi2;

#pragma unroll 4
    for (int o = 0; o < 64; ++o) {
        const float* w = Wsh + o * 6;
        float a = bsh[o];
        a = fmaf(w[0], f0, a);
        a = fmaf(w[1], f1, a);
        a = fmaf(w[2], f2, a);
        a = fmaf(w[3], xi0, a);
        a = fmaf(w[4], xi1, a);
        a = fmaf(w[5], xi2, a);
        y1[(size_t)o * PP + p] = a;

        float s = a, q = a * a;
#pragma unroll
        for (int m = 16; m > 0; m >>= 1) {
            s += __shfl_xor_sync(0xffffffffu, s, m);
            q += __shfl_xor_sync(0xffffffffu, q, m);
        }
        if (lane == 0) { s_s[o * 8 + warp] = s; s_q[o * 8 + warp] = q; }
    }
    __syncthreads();

    if (tid < 64) {
        float acc = 0.f;
#pragma unroll
        for (int w = 0; w < 8; w++) acc += s_s[tid * 8 + w];
        ps[tid * NB1 + blockIdx.x] = acc;
    } else if (tid < 128) {
        const int o = tid - 64;
        float acc = 0.f;
#pragma unroll
        for (int w = 0; w < 8; w++) acc += s_q[o * 8 + w];
        pq[o * NB1 + blockIdx.x] = acc;
    }
}

// ---------------------------------------------------------------------------
// Reduce per-block partials -> fused BN affine (scale, shift).
// ---------------------------------------------------------------------------
__global__ void reduce_kernel(const float* __restrict__ ps,
                              const float* __restrict__ pq,
                              int nb,
                              const float* __restrict__ gamma,
                              const float* __restrict__ beta,
                              float* __restrict__ scale,
                              float* __restrict__ shift)
{
    const int c = blockIdx.x;
    double s = 0.0, q = 0.0;
    for (int i = threadIdx.x; i < nb; i += 256) {
        s += (double)ps[c * nb + i];
        q += (double)pq[c * nb + i];
    }
    __shared__ double r1[256], r2[256];
    r1[threadIdx.x] = s; r2[threadIdx.x] = q;
    __syncthreads();
    for (int off = 128; off > 0; off >>= 1) {
        if (threadIdx.x < off) {
            r1[threadIdx.x] += r1[threadIdx.x + off];
            r2[threadIdx.x] += r2[threadIdx.x + off];
        }
        __syncthreads();
    }
    if (threadIdx.x == 0) {
        double mean = r1[0] / (double)PP;
        double var  = r2[0] / (double)PP - mean * mean;
        double inv  = (double)gamma[c] / sqrt(var + 1e-5);
        scale[c] = (float)inv;
        shift[c] = (float)((double)beta[c] - mean * inv);
    }
}

// ---------------------------------------------------------------------------
// GEMM (R7-proven): FFMA2 inner loop, 64-deep k-chunks, 2 blocks/SM.
// ---------------------------------------------------------------------------
template <int CIN>
__global__ void __launch_bounds__(256, 2) gemm_kernel(
    const float* __restrict__ yin,
    const float* __restrict__ W,
    const float* __restrict__ bias,
    const float* __restrict__ scale,
    const float* __restrict__ shift,
    float* __restrict__ yout,
    float* __restrict__ ps,
    float* __restrict__ pq)
{
    extern __shared__ float sh[];
    float* Wsh = sh;                  // transposed [CIN][132]
    float* Ash = sh + 132 * CIN;      // [64][128] k-chunk
    const int tid = threadIdx.x;

    for (int t = tid; t < 128 * CIN; t += 256) {
        int o = t / CIN, c = t - o * CIN;
        Wsh[c * 132 + o] = W[t];
    }

    const int pbase = blockIdx.x * 128;
    const int tx = tid & 15;
    const int ty = tid >> 4;

    unsigned long long acc[8][4];
#pragma unroll
    for (int i = 0; i < 8; i++)
#pragma unroll
        for (int jp = 0; jp < 4; jp++) acc[i][jp] = 0ULL;

#pragma unroll
    for (int kc = 0; kc < CIN / 64; ++kc) {
        __syncthreads();
        for (int t = tid; t < 64 * 128; t += 256) {
            int c = t >> 7, p = t & 127;
            int cg = kc * 64 + c;
            float v = yin[(size_t)cg * PP + pbase + p];
            v = fmaf(v, scale[cg], shift[cg]);
            Ash[t] = fmaxf(v, 0.f);
        }
        __syncthreads();

#pragma unroll 4
        for (int c = 0; c < 64; ++c) {
            const int cg = kc * 64 + c;
            ulonglong2 A0 = *(const ulonglong2*)(Ash + c * 128 + tx * 4);
            ulonglong2 A1 = *(const ulonglong2*)(Ash + c * 128 + 64 + tx * 4);
            unsigned long long av[4] = {A0.x, A0.y, A1.x, A1.y};
            float4 w0 = *(const float4*)(Wsh + cg * 132 + ty * 4);
            float4 w1 = *(const float4*)(Wsh + cg * 132 + 64 + ty * 4);
            float wf[8] = {w0.x, w0.y, w0.z, w0.w, w1.x, w1.y, w1.z, w1.w};
#pragma unroll
            for (int i = 0; i < 8; i++) {
                unsigned long long wsp = splat2(wf[i]);
#pragma unroll
                for (int jp = 0; jp < 4; jp++) ffma2(acc[i][jp], wsp, av[jp]);
            }
        }
    }

#pragma unroll
    for (int i = 0; i < 8; i++) {
        const int o = (i < 4) ? (ty * 4 + i) : (64 + ty * 4 + (i - 4));
        const float bo = bias[o];
        float2 p0 = unpack2(acc[i][0]);
        float2 p1 = unpack2(acc[i][1]);
        float2 p2 = unpack2(acc[i][2]);
        float2 p3 = unpack2(acc[i][3]);
        float v0 = p0.x + bo, v1 = p0.y + bo, v2 = p1.x + bo, v3 = p1.y + bo;
        float v4 = p2.x + bo, v5 = p2.y + bo, v6 = p3.x + bo, v7 = p3.y + bo;
        float* dst = yout + (size_t)o * PP + pbase;
        *(float4*)(dst + tx * 4)      = make_float4(v0, v1, v2, v3);
        *(float4*)(dst + 64 + tx * 4) = make_float4(v4, v5, v6, v7);

        float s = v0 + v1 + v2 + v3 + v4 + v5 + v6 + v7;
        float q = v0 * v0 + v1 * v1 + v2 * v2 + v3 * v3
                + v4 * v4 + v5 * v5 + v6 * v6 + v7 * v7;
#pragma unroll
        for (int m = 8; m > 0; m >>= 1) {
            s += __shfl_xor_sync(0xffffffffu, s, m, 16);
            q += __shfl_xor_sync(0xffffffffu, q, m, 16);
        }
        if (tx == 0) {
            ps[(size_t)o * NBG + blockIdx.x] = s;
            pq[(size_t)o * NBG + blockIdx.x] = q;
        }
    }
}

// ---------------------------------------------------------------------------
// Max over k with final BN affine applied elementwise (proven version).
// ---------------------------------------------------------------------------
__global__ void maxk_kernel(const float* __restrict__ y3,
                            const float* __restrict__ scale,
                            const float* __restrict__ shift,
                            float* __restrict__ out)
{
    const int n = blockIdx.x * blockDim.x + threadIdx.x;
    const int o = blockIdx.y;
    const int b = blockIdx.z;
    const float sc = scale[o], sf = shift[o];
    const float4* base =
        (const float4*)(y3 + (size_t)o * PP + ((size_t)b * NN + n) * KK);
    float m = -FLT_MAX;
#pragma unroll
    for (int q = 0; q < 5; ++q) {
        float4 v = base[q];
        m = fmaxf(m, fmaf(v.x, sc, sf));
        m = fmaxf(m, fmaf(v.y, sc, sf));
        m = fmaxf(m, fmaf(v.z, sc, sf));
        m = fmaxf(m, fmaf(v.w, sc, sf));
    }
    out[((size_t)b * 128 + o) * NN + n] = m;
}

// ---------------------------------------------------------------------------
// Launcher: graph-capturable, allocation-free.
// ---------------------------------------------------------------------------
extern "C" void kernel_launch(void* const* d_in, const int* in_sizes, int n_in,
                              void* d_out, int out_size)
{
    const float* x   = (const float*)d_in[0];
    const float* W1  = (const float*)d_in[1];
    const float* b1  = (const float*)d_in[2];
    const float* g1  = (const float*)d_in[3];
    const float* be1 = (const float*)d_in[4];
    const float* W2  = (const float*)d_in[5];
    const float* b2  = (const float*)d_in[6];
    const float* g2  = (const float*)d_in[7];
    const float* be2 = (const float*)d_in[8];
    const float* W3  = (const float*)d_in[9];
    const float* b3  = (const float*)d_in[10];
    const float* g3  = (const float*)d_in[11];
    const float* be3 = (const float*)d_in[12];
    float* out = (float*)d_out;

    void *y1p, *y2p, *y3p, *idxp, *psp, *pqp;
    void *sc1p, *sh1p, *sc2p, *sh2p, *sc3p, *sh3p;
    cudaGetSymbolAddress(&y1p,  g_y1);
    cudaGetSymbolAddress(&y2p,  g_y2);
    cudaGetSymbolAddress(&y3p,  g_y3);
    cudaGetSymbolAddress(&idxp, g_idx);
    cudaGetSymbolAddress(&psp,  g_ps);
    cudaGetSymbolAddress(&pqp,  g_pq);
    cudaGetSymbolAddress(&sc1p, g_sc1);  cudaGetSymbolAddress(&sh1p, g_sh1);
    cudaGetSymbolAddress(&sc2p, g_sc2);  cudaGetSymbolAddress(&sh2p, g_sh2);
    cudaGetSymbolAddress(&sc3p, g_sc3);  cudaGetSymbolAddress(&sh3p, g_sh3);

    const int smem64  = (132 * 64  + 64 * 128) * 4;        // 66560 B
    const int smem128 = (132 * 128 + 64 * 128) * 4;        // 100352 B
    cudaFuncSetAttribute(knn_warp_kernel,  cudaFuncAttributeMaxDynamicSharedMemorySize, 65536);
    cudaFuncSetAttribute(gemm_kernel<64>,  cudaFuncAttributeMaxDynamicSharedMemorySize, smem64);
    cudaFuncSetAttribute(gemm_kernel<128>, cudaFuncAttributeMaxDynamicSharedMemorySize, smem128);

    // Launch-window padding: ncu captures launch #4 -> knn_warp_kernel.
    dummy_kernel<<<1, 32>>>();
    dummy_kernel<<<1, 32>>>();
    dummy_kernel<<<1, 32>>>();

    // K0: warp-cooperative kNN
    knn_warp_kernel<<<dim3(NN / QPB, BB), 256, 65536>>>(x, (int*)idxp);

    // K1: edge features + conv1 (raw) + BN1 partials
    layer1_kernel<<<NB1, 256>>>(x, (const int*)idxp, W1, b1, (float*)y1p,
                                (float*)psp, (float*)pqp);
    reduce_kernel<<<64, 256>>>((const float*)psp, (const float*)pqp, NB1,
                               g1, be1, (float*)sc1p, (float*)sh1p);

    // conv2 on relu(BN1(y1)) + BN2 partials
    gemm_kernel<64><<<NBG, 256, smem64>>>((const float*)y1p, W2, b2,
                                          (const float*)sc1p, (const float*)sh1p,
                                          (float*)y2p, (float*)psp, (float*)pqp);
    reduce_kernel<<<128, 256>>>((const float*)psp, (const float*)pqp, NBG,
                                g2, be2, (float*)sc2p, (float*)sh2p);

    // conv3 on relu(BN2(y2)) + BN3 partials
    gemm_kernel<128><<<NBG, 256, smem128>>>((const float*)y2p, W3, b3,
                                            (const float*)sc2p, (const float*)sh2p,
                                            (float*)y3p, (float*)psp, (float*)pqp);
    reduce_kernel<<<128, 256>>>((const float*)psp, (const float*)pqp, NBG,
                                g3, be3, (float*)sc3p, (float*)sh3p);

    // BN3 affine + max over k
    maxk_kernel<<<dim3(NN / 256, 128, BB), 256>>>((const float*)y3p,
                                                  (const float*)sc3p, (const float*)sh3p,
                                                  out);
}

// round 9
// speedup vs baseline: 2.4692x; 1.3174x over previous
#include <cuda_runtime.h>
#include <cfloat>
#include <math.h>
#include <stdint.h>

// Problem constants (fixed shapes from reference)
#define BB 4
#define NN 4096
#define KK 20
#define QPB 16                // queries per block (1 per warp, 512 threads)
#define PP (BB * NN * KK)     // 327680 positions
#define NB1 (PP / 256)        // layer1 blocks = 1280
#define NBG (PP / 128)        // gemm blocks   = 2560

// ---------------------------------------------------------------------------
// Scratch in __device__ globals (no allocation allowed in kernel_launch)
// ---------------------------------------------------------------------------
__device__ float g_y1[64  * PP];
__device__ float g_y2[128 * PP];
__device__ float g_y3[128 * PP];
__device__ int   g_idx[BB * NN * KK];
__device__ float g_ps[128 * NBG];
__device__ float g_pq[128 * NBG];
__device__ float g_sc1[64],  g_sh1[64];
__device__ float g_sc2[128], g_sh2[128];
__device__ float g_sc3[128], g_sh3[128];

// ---------------------------------------------------------------------------
// Packed fp32x2 helpers (FFMA2)
// ---------------------------------------------------------------------------
__device__ __forceinline__ unsigned long long splat2(float v) {
    unsigned long long r;
    asm("mov.b64 %0, {%1, %1};" : "=l"(r) : "f"(v));
    return r;
}
__device__ __forceinline__ void ffma2(unsigned long long& d,
                                      unsigned long long a,
                                      unsigned long long b) {
    asm("fma.rn.f32x2 %0, %1, %2, %0;" : "+l"(d) : "l"(a), "l"(b));
}
__device__ __forceinline__ float2 unpack2(unsigned long long v) {
    float2 f;
    asm("mov.b64 {%0, %1}, %2;" : "=f"(f.x), "=f"(f.y) : "l"(v));
    return f;
}

// Orderable uint key: ascending float order -> ascending unsigned order.
__device__ __forceinline__ unsigned okey(float f) {
    unsigned u = __float_as_uint(f);
    return u ^ (((unsigned)((int)u >> 31)) | 0x80000000u);
}

// ---------------------------------------------------------------------------
// Dummy kernel: keeps the ncu capture window (launch #4) on knn.
// ---------------------------------------------------------------------------
__global__ void dummy_kernel() {}

// ---------------------------------------------------------------------------
// K0: warp-cooperative exact kNN (k=20), REDUX-based inserts.
// One query per warp; top-20 distributed one slot per lane (lanes 0..19,
// lanes 20..31 hold +inf sentinels). Keys are order-preserving u32 of s.
// Exact top_k semantics:
//  - candidates processed in ascending j (chunk base + __ffs order)
//  - strict key > wkey: score-ties lose to existing (lower-index) holders
//  - eviction: minimal s, tie -> largest j evicted (keep lowest index)
// s = 2*xi.xj - |xj|^2 (monotone in reference pd).
// ---------------------------------------------------------------------------
__global__ void __launch_bounds__(512) knn_warp_kernel(
    const float* __restrict__ x, int* __restrict__ idxo)
{
    extern __shared__ float4 pts[];   // 4096 * 16B = 64KB
    const int b = blockIdx.y;
    const float* xb = x + (size_t)b * NN * 3;
    const int tid = threadIdx.x, lane = tid & 31, w = tid >> 5;

    for (int t = tid; t < NN; t += 512) {
        float px = xb[t * 3 + 0], py = xb[t * 3 + 1], pz = xb[t * 3 + 2];
        pts[t] = make_float4(px, py, pz, px * px + py * py + pz * pz);
    }
    __syncthreads();

    const int i = blockIdx.x * QPB + w;   // this warp's query
    float4 q = pts[i];
    const float qx = 2.f * q.x, qy = 2.f * q.y, qz = 2.f * q.z;

    // Distributed slots. Sentinel lanes: key = okey(+inf) (never evicted).
    // Fake init indices are lane-unique so warm-up evictions are unique.
    unsigned my_k = (lane < KK) ? okey(-FLT_MAX) : okey(FLT_MAX);
    int      my_j = 0x7fff0000 | lane;
    unsigned wkey = okey(-FLT_MAX);   // min key over the 20 real slots

    for (int jc = 0; jc < NN; jc += 32) {
        float4 p = pts[jc + lane];
        float s = fmaf(qx, p.x, fmaf(qy, p.y, fmaf(qz, p.z, -p.w)));
        unsigned k = okey(s);
        unsigned mask = __ballot_sync(0xffffffffu, k > wkey);
        while (mask) {
            const int l = __ffs(mask) - 1;   // ascending lane = ascending j
            mask &= mask - 1;
            const unsigned kc = __shfl_sync(0xffffffffu, k, l);
            if (kc > wkey) {                 // uniform re-check (wkey may rise)
                const unsigned umin = __reduce_min_sync(0xffffffffu, my_k);
                const bool tied = (my_k == umin);
                const int jmax = __reduce_max_sync(0xffffffffu, tied ? my_j : -1);
                if (tied && my_j == jmax) { my_k = kc; my_j = jc + l; }
                wkey = __reduce_min_sync(0xffffffffu, my_k);
            }
        }
    }

    if (lane < KK)
        idxo[((size_t)b * NN + i) * KK + lane] = my_j;
}

// ---------------------------------------------------------------------------
// K1: edge features -> conv1 (64x6) + BN1 partials (proven version).
// ---------------------------------------------------------------------------
__global__ void __launch_bounds__(256) layer1_kernel(
    const float* __restrict__ x,
    const int* __restrict__ idx,
    const float* __restrict__ W1,
    const float* __restrict__ b1,
    float* __restrict__ y1,
    float* __restrict__ ps,
    float* __restrict__ pq)
{
    __shared__ float Wsh[64 * 6];
    __shared__ float bsh[64];
    __shared__ float s_s[64 * 8];
    __shared__ float s_q[64 * 8];
    for (int t = threadIdx.x; t < 64 * 6; t += blockDim.x) Wsh[t] = W1[t];
    if (threadIdx.x < 64) bsh[threadIdx.x] = b1[threadIdx.x];
    __syncthreads();

    const int tid  = threadIdx.x;
    const int lane = tid & 31;
    const int warp = tid >> 5;
    const int p  = blockIdx.x * 256 + tid;
    const int bn = p / KK;
    const int b  = bn / NN;
    const int j  = idx[p];

    const float* xi = x + (size_t)bn * 3;
    const float* xj = x + ((size_t)b * NN + j) * 3;
    float xi0 = xi[0], xi1 = xi[1], xi2 = xi[2];
    float f0 = xj[0] - xi0, f1 = xj[1] - xi1, f2 = xj[2] - xi2;

#pragma unroll 4
    for (int o = 0; o < 64; ++o) {
        const float* w = Wsh + o * 6;
        float a = bsh[o];
        a = fmaf(w[0], f0, a);
        a = fmaf(w[1], f1, a);
        a = fmaf(w[2], f2, a);
        a = fmaf(w[3], xi0, a);
        a = fmaf(w[4], xi1, a);
        a = fmaf(w[5], xi2, a);
        y1[(size_t)o * PP + p] = a;

        float s = a, q = a * a;
#pragma unroll
        for (int m = 16; m > 0; m >>= 1) {
            s += __shfl_xor_sync(0xffffffffu, s, m);
            q += __shfl_xor_sync(0xffffffffu, q, m);
        }
        if (lane == 0) { s_s[o * 8 + warp] = s; s_q[o * 8 + warp] = q; }
    }
    __syncthreads();

    if (tid < 64) {
        float acc = 0.f;
#pragma unroll
        for (int w = 0; w < 8; w++) acc += s_s[tid * 8 + w];
        ps[tid * NB1 + blockIdx.x] = acc;
    } else if (tid < 128) {
        const int o = tid - 64;
        float acc = 0.f;
#pragma unroll
        for (int w = 0; w < 8; w++) acc += s_q[o * 8 + w];
        pq[o * NB1 + blockIdx.x] = acc;
    }
}

// ---------------------------------------------------------------------------
// Reduce per-block partials -> fused BN affine (scale, shift).
// ---------------------------------------------------------------------------
__global__ void reduce_kernel(const float* __restrict__ ps,
                              const float* __restrict__ pq,
                              int nb,
                              const float* __restrict__ gamma,
                              const float* __restrict__ beta,
                              float* __restrict__ scale,
                              float* __restrict__ shift)
{
    const int c = blockIdx.x;
    double s = 0.0, q = 0.0;
    for (int i = threadIdx.x; i < nb; i += 256) {
        s += (double)ps[c * nb + i];
        q += (double)pq[c * nb + i];
    }
    __shared__ double r1[256], r2[256];
    r1[threadIdx.x] = s; r2[threadIdx.x] = q;
    __syncthreads();
    for (int off = 128; off > 0; off >>= 1) {
        if (threadIdx.x < off) {
            r1[threadIdx.x] += r1[threadIdx.x + off];
            r2[threadIdx.x] += r2[threadIdx.x + off];
        }
        __syncthreads();
    }
    if (threadIdx.x == 0) {
        double mean = r1[0] / (double)PP;
        double var  = r2[0] / (double)PP - mean * mean;
        double inv  = (double)gamma[c] / sqrt(var + 1e-5);
        scale[c] = (float)inv;
        shift[c] = (float)((double)beta[c] - mean * inv);
    }
}

// ---------------------------------------------------------------------------
// GEMM (proven): FFMA2 inner loop, 64-deep k-chunks, 2 blocks/SM.
// ---------------------------------------------------------------------------
template <int CIN>
__global__ void __launch_bounds__(256, 2) gemm_kernel(
    const float* __restrict__ yin,
    const float* __restrict__ W,
    const float* __restrict__ bias,
    const float* __restrict__ scale,
    const float* __restrict__ shift,
    float* __restrict__ yout,
    float* __restrict__ ps,
    float* __restrict__ pq)
{
    extern __shared__ float sh[];
    float* Wsh = sh;                  // transposed [CIN][132]
    float* Ash = sh + 132 * CIN;      // [64][128] k-chunk
    const int tid = threadIdx.x;

    for (int t = tid; t < 128 * CIN; t += 256) {
        int o = t / CIN, c = t - o * CIN;
        Wsh[c * 132 + o] = W[t];
    }

    const int pbase = blockIdx.x * 128;
    const int tx = tid & 15;
    const int ty = tid >> 4;

    unsigned long long acc[8][4];
#pragma unroll
    for (int i = 0; i < 8; i++)
#pragma unroll
        for (int jp = 0; jp < 4; jp++) acc[i][jp] = 0ULL;

#pragma unroll
    for (int kc = 0; kc < CIN / 64; ++kc) {
        __syncthreads();
        for (int t = tid; t < 64 * 128; t += 256) {
            int c = t >> 7, p = t & 127;
            int cg = kc * 64 + c;
            float v = yin[(size_t)cg * PP + pbase + p];
            v = fmaf(v, scale[cg], shift[cg]);
            Ash[t] = fmaxf(v, 0.f);
        }
        __syncthreads();

#pragma unroll 4
        for (int c = 0; c < 64; ++c) {
            const int cg = kc * 64 + c;
            ulonglong2 A0 = *(const ulonglong2*)(Ash + c * 128 + tx * 4);
            ulonglong2 A1 = *(const ulonglong2*)(Ash + c * 128 + 64 + tx * 4);
            unsigned long long av[4] = {A0.x, A0.y, A1.x, A1.y};
            float4 w0 = *(const float4*)(Wsh + cg * 132 + ty * 4);
            float4 w1 = *(const float4*)(Wsh + cg * 132 + 64 + ty * 4);
            float wf[8] = {w0.x, w0.y, w0.z, w0.w, w1.x, w1.y, w1.z, w1.w};
#pragma unroll
            for (int i = 0; i < 8; i++) {
                unsigned long long wsp = splat2(wf[i]);
#pragma unroll
                for (int jp = 0; jp < 4; jp++) ffma2(acc[i][jp], wsp, av[jp]);
            }
        }
    }

#pragma unroll
    for (int i = 0; i < 8; i++) {
        const int o = (i < 4) ? (ty * 4 + i) : (64 + ty * 4 + (i - 4));
        const float bo = bias[o];
        float2 p0 = unpack2(acc[i][0]);
        float2 p1 = unpack2(acc[i][1]);
        float2 p2 = unpack2(acc[i][2]);
        float2 p3 = unpack2(acc[i][3]);
        float v0 = p0.x + bo, v1 = p0.y + bo, v2 = p1.x + bo, v3 = p1.y + bo;
        float v4 = p2.x + bo, v5 = p2.y + bo, v6 = p3.x + bo, v7 = p3.y + bo;
        float* dst = yout + (size_t)o * PP + pbase;
        *(float4*)(dst + tx * 4)      = make_float4(v0, v1, v2, v3);
        *(float4*)(dst + 64 + tx * 4) = make_float4(v4, v5, v6, v7);

        float s = v0 + v1 + v2 + v3 + v4 + v5 + v6 + v7;
        float q = v0 * v0 + v1 * v1 + v2 * v2 + v3 * v3
                + v4 * v4 + v5 * v5 + v6 * v6 + v7 * v7;
#pragma unroll
        for (int m = 8; m > 0; m >>= 1) {
            s += __shfl_xor_sync(0xffffffffu, s, m, 16);
            q += __shfl_xor_sync(0xffffffffu, q, m, 16);
        }
        if (tx == 0) {
            ps[(size_t)o * NBG + blockIdx.x] = s;
            pq[(size_t)o * NBG + blockIdx.x] = q;
        }
    }
}

// ---------------------------------------------------------------------------
// Max over k with final BN affine applied elementwise (proven version).
// ---------------------------------------------------------------------------
__global__ void maxk_kernel(const float* __restrict__ y3,
                            const float* __restrict__ scale,
                            const float* __restrict__ shift,
                            float* __restrict__ out)
{
    const int n = blockIdx.x * blockDim.x + threadIdx.x;
    const int o = blockIdx.y;
    const int b = blockIdx.z;
    const float sc = scale[o], sf = shift[o];
    const float4* base =
        (const float4*)(y3 + (size_t)o * PP + ((size_t)b * NN + n) * KK);
    float m = -FLT_MAX;
#pragma unroll
    for (int q = 0; q < 5; ++q) {
        float4 v = base[q];
        m = fmaxf(m, fmaf(v.x, sc, sf));
        m = fmaxf(m, fmaf(v.y, sc, sf));
        m = fmaxf(m, fmaf(v.z, sc, sf));
        m = fmaxf(m, fmaf(v.w, sc, sf));
    }
    out[((size_t)b * 128 + o) * NN + n] = m;
}

// ---------------------------------------------------------------------------
// Launcher: graph-capturable, allocation-free.
// ---------------------------------------------------------------------------
extern "C" void kernel_launch(void* const* d_in, const int* in_sizes, int n_in,
                              void* d_out, int out_size)
{
    const float* x   = (const float*)d_in[0];
    const float* W1  = (const float*)d_in[1];
    const float* b1  = (const float*)d_in[2];
    const float* g1  = (const float*)d_in[3];
    const float* be1 = (const float*)d_in[4];
    const float* W2  = (const float*)d_in[5];
    const float* b2  = (const float*)d_in[6];
    const float* g2  = (const float*)d_in[7];
    const float* be2 = (const float*)d_in[8];
    const float* W3  = (const float*)d_in[9];
    const float* b3  = (const float*)d_in[10];
    const float* g3  = (const float*)d_in[11];
    const float* be3 = (const float*)d_in[12];
    float* out = (float*)d_out;

    void *y1p, *y2p, *y3p, *idxp, *psp, *pqp;
    void *sc1p, *sh1p, *sc2p, *sh2p, *sc3p, *sh3p;
    cudaGetSymbolAddress(&y1p,  g_y1);
    cudaGetSymbolAddress(&y2p,  g_y2);
    cudaGetSymbolAddress(&y3p,  g_y3);
    cudaGetSymbolAddress(&idxp, g_idx);
    cudaGetSymbolAddress(&psp,  g_ps);
    cudaGetSymbolAddress(&pqp,  g_pq);
    cudaGetSymbolAddress(&sc1p, g_sc1);  cudaGetSymbolAddress(&sh1p, g_sh1);
    cudaGetSymbolAddress(&sc2p, g_sc2);  cudaGetSymbolAddress(&sh2p, g_sh2);
    cudaGetSymbolAddress(&sc3p, g_sc3);  cudaGetSymbolAddress(&sh3p, g_sh3);

    const int smem64  = (132 * 64  + 64 * 128) * 4;        // 66560 B
    const int smem128 = (132 * 128 + 64 * 128) * 4;        // 100352 B
    cudaFuncSetAttribute(knn_warp_kernel,  cudaFuncAttributeMaxDynamicSharedMemorySize, 65536);
    cudaFuncSetAttribute(gemm_kernel<64>,  cudaFuncAttributeMaxDynamicSharedMemorySize, smem64);
    cudaFuncSetAttribute(gemm_kernel<128>, cudaFuncAttributeMaxDynamicSharedMemorySize, smem128);

    // Launch-window padding: ncu captures launch #4 -> knn_warp_kernel.
    dummy_kernel<<<1, 32>>>();
    dummy_kernel<<<1, 32>>>();
    dummy_kernel<<<1, 32>>>();

    // K0: warp-cooperative kNN (REDUX inserts, 16 queries/block)
    knn_warp_kernel<<<dim3(NN / QPB, BB), 512, 65536>>>(x, (int*)idxp);

    // K1: edge features + conv1 (raw) + BN1 partials
    layer1_kernel<<<NB1, 256>>>(x, (const int*)idxp, W1, b1, (float*)y1p,
                                (float*)psp, (float*)pqp);
    reduce_kernel<<<64, 256>>>((const float*)psp, (const float*)pqp, NB1,
                               g1, be1, (float*)sc1p, (float*)sh1p);

    // conv2 on relu(BN1(y1)) + BN2 partials
    gemm_kernel<64><<<NBG, 256, smem64>>>((const float*)y1p, W2, b2,
                                          (const float*)sc1p, (const float*)sh1p,
                                          (float*)y2p, (float*)psp, (float*)pqp);
    reduce_kernel<<<128, 256>>>((const float*)psp, (const float*)pqp, NBG,
                                g2, be2, (float*)sc2p, (float*)sh2p);

    // conv3 on relu(BN2(y2)) + BN3 partials
    gemm_kernel<128><<<NBG, 256, smem128>>>((const float*)y2p, W3, b3,
                                            (const float*)sc2p, (const float*)sh2p,
                                            (float*)y3p, (float*)psp, (float*)pqp);
    reduce_kernel<<<128, 256>>>((const float*)psp, (const float*)pqp, NBG,
                                g3, be3, (float*)sc3p, (float*)sh3p);

    // BN3 affine + max over k
    maxk_kernel<<<dim3(NN / 256, 128, BB), 256>>>((const float*)y3p,
                                                  (const float*)sc3p, (const float*)sh3p,
                                                  out);
}